// round 5
// baseline (speedup 1.0000x reference)
#include <cuda_runtime.h>
#include <cstdint>

typedef unsigned long long ull;

#define B_TOTAL   131072
#define DIMN      256
#define NLAYERS   6
#define MTILE     64
#define NTHREADS  256

// output layout: h_final [B,256] then aligns[6,B,3], divs[6,B,3], tens[6,B,3]
#define OUT_ALIGN 33554432
#define OUT_DIV   35913728
#define OUT_TEN   38273024

// smem float offsets
#define SM_H   0        // 16384 : h tile [64][256]
#define SM_Z   16384    // 16384 : tanh tile [64][256]
#define SM_W   32768    // 16384 : W staging, 2 buffers x 8192 floats (4096 float2)
#define SM_A   49152    // 768   : normalized anchors [3][256]
#define SM_B1  49920    // 256
#define SM_B2  50176    // 256
#define SM_SS  50432    // 64    : per-row ||h||^2
#define SM_D0  50496    // 64    : per-row <h,a0>
#define SM_D1  50560
#define SM_D2  50624
#define SM_TOTALF 50688
#define SMEM_BYTES (SM_TOTALF * 4)

// W1/W2 pre-transposed to k-pair-major: g_Wt[kk*256 + n] = {W[n][2kk], W[n][2kk+1]}
__device__ __align__(16) float2 g_Wt1[128 * 256];
__device__ __align__(16) float2 g_Wt2[128 * 256];
__device__ __align__(16) float  g_an[3 * 256];

// ---------------------------------------------------------------- helpers
__device__ __forceinline__ void fma2(ull& d, ull a, ull b) {
    asm("fma.rn.f32x2 %0, %1, %2, %0;" : "+l"(d) : "l"(a), "l"(b));
}
__device__ __forceinline__ float pair_sum(ull v) {
    return __uint_as_float((unsigned)v) + __uint_as_float((unsigned)(v >> 32));
}
__device__ __forceinline__ void cp_async16(float* s, const float4* g) {
    unsigned sa = (unsigned)__cvta_generic_to_shared(s);
    asm volatile("cp.async.cg.shared.global [%0], [%1], 16;" :: "r"(sa), "l"(g));
}
__device__ __forceinline__ void cp_commit() { asm volatile("cp.async.commit_group;"); }
template <int N> __device__ __forceinline__ void cp_wait() {
    asm volatile("cp.async.wait_group %0;" :: "n"(N));
}
__device__ __forceinline__ void reduce4(float& a, float& b, float& c, float& d) {
#pragma unroll
    for (int off = 16; off > 0; off >>= 1) {
        a += __shfl_xor_sync(0xffffffffu, a, off);
        b += __shfl_xor_sync(0xffffffffu, b, off);
        c += __shfl_xor_sync(0xffffffffu, c, off);
        d += __shfl_xor_sync(0xffffffffu, d, off);
    }
}

// copy one 32KB chunk (16 kk-pairs x 256 cols of float2) into smem
__device__ __forceinline__ void copy_chunk(float* dst, const float4* src, int tid) {
#pragma unroll
    for (int q = 0; q < 8; q++)
        cp_async16(dst + (tid + 256 * q) * 4, src + tid + 256 * q);
}

// D[m, n] += sum_k A[m, k] * W[n, k]   with k-paired f32x2 accumulators.
// A_s: [64][256] fp32 row-major smem.  Bg4: k-pair-major float2 matrix (as float4*).
__device__ __forceinline__ void gemm64(const float* __restrict__ A_s,
                                       const float4* __restrict__ Bg4,
                                       float* wreg, ull (&acc)[8][8],
                                       int tid, int wy, int tx) {
#pragma unroll
    for (int r = 0; r < 8; r++)
#pragma unroll
        for (int j = 0; j < 8; j++) acc[r][j] = 0ull;

    copy_chunk(wreg, Bg4, tid);
    cp_commit();

#pragma unroll 1
    for (int c = 0; c < 8; c++) {
        if (c < 7) {
            copy_chunk(wreg + ((c + 1) & 1) * 8192, Bg4 + (c + 1) * 2048, tid);
            cp_commit();
            cp_wait<1>();
        } else {
            cp_wait<0>();
        }
        __syncthreads();

        const float* wb = wreg + (c & 1) * 8192;       // float2 region, as floats
        const float* Ab = A_s + wy * 8 * 256 + c * 32; // this warp's 8 rows, chunk k-base
#pragma unroll
        for (int kk = 0; kk < 16; kk++) {
            ull bv[8];
#pragma unroll
            for (int j = 0; j < 8; j++)
                bv[j] = *(const ull*)(wb + 2 * (kk * 256 + tx + 32 * j));
#pragma unroll
            for (int r = 0; r < 8; r++) {
                ull av = *(const ull*)(Ab + r * 256 + 2 * kk);
#pragma unroll
                for (int j = 0; j < 8; j++) fma2(acc[r][j], av, bv[j]);
            }
        }
        __syncthreads();
    }
}

// ---------------------------------------------------------------- prep kernel
__global__ void prep_kernel(const float* __restrict__ W1, const float* __restrict__ W2,
                            const float* __restrict__ anchors) {
    int t = blockIdx.x * blockDim.x + threadIdx.x;
    for (int i = t; i < 128 * 256; i += gridDim.x * blockDim.x) {
        int kk = i >> 8, n = i & 255;
        g_Wt1[i] = make_float2(W1[n * 256 + 2 * kk], W1[n * 256 + 2 * kk + 1]);
        g_Wt2[i] = make_float2(W2[n * 256 + 2 * kk], W2[n * 256 + 2 * kk + 1]);
    }
    if (blockIdx.x == 0 && threadIdx.x < 3) {
        int a = threadIdx.x;
        float ss = 0.f;
        for (int k = 0; k < 256; k++) { float v = anchors[a * 256 + k]; ss += v * v; }
        float inv = 1.f / fmaxf(sqrtf(ss), 1e-12f);
        for (int k = 0; k < 256; k++) g_an[a * 256 + k] = anchors[a * 256 + k] * inv;
    }
}

// ---------------------------------------------------------------- main fused kernel
__global__ void __launch_bounds__(NTHREADS, 1)
collapse_kernel(const float* __restrict__ h0, const float* __restrict__ b1,
                const float* __restrict__ b2, float* __restrict__ out) {
    extern __shared__ float sm[];
    float* h_s  = sm + SM_H;
    float* z_s  = sm + SM_Z;
    float* w_s  = sm + SM_W;
    float* a_s  = sm + SM_A;
    float* b1_s = sm + SM_B1;
    float* b2_s = sm + SM_B2;
    float* stss = sm + SM_SS;
    float* std0 = sm + SM_D0;
    float* std1 = sm + SM_D1;
    float* std2 = sm + SM_D2;

    const int tid  = threadIdx.x;
    const int wy   = tid >> 5;   // warp id = row group (8 rows)
    const int tx   = tid & 31;
    const int row0 = blockIdx.x * MTILE;

    // ---- load h tile, anchors, biases
    {
        const float4* hv = (const float4*)(h0 + (size_t)row0 * DIMN);
        float4* hs = (float4*)h_s;
#pragma unroll
        for (int q = 0; q < 16; q++) hs[tid + 256 * q] = hv[tid + 256 * q];
        if (tid < 192) ((float4*)a_s)[tid] = ((const float4*)g_an)[tid];
        if (tid < 64) ((float4*)b1_s)[tid] = ((const float4*)b1)[tid];
        else if (tid < 128) ((float4*)b2_s)[tid - 64] = ((const float4*)b2)[tid - 64];
    }
    __syncthreads();

    // ---- initial per-row stats: ||h||^2, <h, a_i>
#pragma unroll
    for (int r = 0; r < 8; r++) {
        int m = wy * 8 + r;
        float p0 = 0.f, p1 = 0.f, p2 = 0.f, p3 = 0.f;
#pragma unroll
        for (int j = 0; j < 8; j++) {
            int col = tx + 32 * j;
            float hv = h_s[m * 256 + col];
            p0 += hv * hv;
            p1 += hv * a_s[col];
            p2 += hv * a_s[256 + col];
            p3 += hv * a_s[512 + col];
        }
        reduce4(p0, p1, p2, p3);
        if (tx == 0) { stss[m] = p0; std0[m] = p1; std1[m] = p2; std2[m] = p3; }
    }

    ull acc[8][8];

    for (int l = 0; l < NLAYERS; l++) {
        __syncthreads();  // stats + h_s visible to all

        // ---- traces for this layer (one thread per row)
        if (tid < MTILE) {
            float ss = stss[tid];
            float inv = 1.f / fmaxf(sqrtf(ss), 1e-12f);
            float dts[3] = { std0[tid], std1[tid], std2[tid] };
            size_t base = (size_t)(l * B_TOTAL + row0 + tid) * 3;
#pragma unroll
            for (int a = 0; a < 3; a++) {
                float al = dts[a] * inv;
                float dv = 1.f - al;
                out[OUT_ALIGN + base + a] = al;
                out[OUT_DIV   + base + a] = dv;
                out[OUT_TEN   + base + a] = fabsf(dv);
            }
        }

        // ---- GEMM1: pre = h @ W1^T ; z = tanh(pre + b1)
        gemm64(h_s, (const float4*)g_Wt1, w_s, acc, tid, wy, tx);
#pragma unroll
        for (int r = 0; r < 8; r++) {
            int m = wy * 8 + r;
#pragma unroll
            for (int j = 0; j < 8; j++) {
                int col = tx + 32 * j;
                z_s[m * 256 + col] = tanhf(pair_sum(acc[r][j]) + b1_s[col]);
            }
        }
        __syncthreads();

        // ---- GEMM2: delta = z @ W2^T (+ b2 in epilogue)
        gemm64(z_s, (const float4*)g_Wt2, w_s, acc, tid, wy, tx);

        // ---- epilogue: force + update + clip + stats for next layer
#pragma unroll
        for (int r = 0; r < 8; r++) {
            int m = wy * 8 + r;
            float ss = stss[m], d0 = std0[m], d1 = std1[m], d2 = std2[m];
            float inv = 1.f / fmaxf(sqrtf(ss), 1e-12f);
            float dv0 = 1.f - d0 * inv, dv1 = 1.f - d1 * inv, dv2 = 1.f - d2 * inv;
            float nd0 = sqrtf(fmaxf(ss - 2.f * d0 + 1.f, 0.f));
            float nd1 = sqrtf(fmaxf(ss - 2.f * d1 + 1.f, 0.f));
            float nd2 = sqrtf(fmaxf(ss - 2.f * d2 + 1.f, 0.f));
            float ca0 = 0.1f * dv0 / fmaxf(nd0, 1e-12f);
            float ca1 = 0.1f * dv1 / fmaxf(nd1, 1e-12f);
            float ca2 = 0.1f * dv2 / fmaxf(nd2, 1e-12f);
            float hmul = 1.f - (ca0 + ca1 + ca2);

            float v[8];
            float p0 = 0.f, p1 = 0.f, p2 = 0.f, p3 = 0.f;
#pragma unroll
            for (int j = 0; j < 8; j++) {
                int col = tx + 32 * j;
                float hv = h_s[m * 256 + col];
                float dl = pair_sum(acc[r][j]) + b2_s[col];
                float a0 = a_s[col], a1 = a_s[256 + col], a2 = a_s[512 + col];
                float x = hv * hmul + dl + ca0 * a0 + ca1 * a1 + ca2 * a2;
                v[j] = x;
                p0 += x * x; p1 += x * a0; p2 += x * a1; p3 += x * a2;
            }
            reduce4(p0, p1, p2, p3);
            float n = sqrtf(p0);
            float s = (n > 10.f) ? (10.f / (n + 1e-8f)) : 1.f;
#pragma unroll
            for (int j = 0; j < 8; j++) h_s[m * 256 + tx + 32 * j] = v[j] * s;
            if (tx == 0) {
                stss[m] = p0 * s * s;
                std0[m] = p1 * s; std1[m] = p2 * s; std2[m] = p3 * s;
            }
        }
    }
    __syncthreads();

    // ---- store h_final
    {
        float4* ov = (float4*)(out + (size_t)row0 * DIMN);
        const float4* hs = (const float4*)h_s;
#pragma unroll
        for (int q = 0; q < 16; q++) ov[tid + 256 * q] = hs[tid + 256 * q];
    }
}

// ---------------------------------------------------------------- launch
extern "C" void kernel_launch(void* const* d_in, const int* in_sizes, int n_in,
                              void* d_out, int out_size) {
    const float* h0      = (const float*)d_in[0];
    const float* W1      = (const float*)d_in[1];
    const float* b1      = (const float*)d_in[2];
    const float* W2      = (const float*)d_in[3];
    const float* b2      = (const float*)d_in[4];
    const float* anchors = (const float*)d_in[5];
    float* out = (float*)d_out;

    (void)in_sizes; (void)n_in; (void)out_size;

    cudaFuncSetAttribute(collapse_kernel,
                         cudaFuncAttributeMaxDynamicSharedMemorySize, SMEM_BYTES);

    prep_kernel<<<64, 256>>>(W1, W2, anchors);
    collapse_kernel<<<B_TOTAL / MTILE, NTHREADS, SMEM_BYTES>>>(h0, b1, b2, out);
}

// round 6
// speedup vs baseline: 1.0557x; 1.0557x over previous
#include <cuda_runtime.h>
#include <cstdint>

typedef unsigned long long ull;

#define B_TOTAL   131072
#define DIMN      256
#define NLAYERS   6
#define MTILE     64
#define NTHREADS  256

// output layout: h_final [B,256] then aligns[6,B,3], divs[6,B,3], tens[6,B,3]
#define OUT_ALIGN 33554432
#define OUT_DIV   35913728
#define OUT_TEN   38273024

// smem float offsets
#define SM_H   0        // 16384 : h tile [64][256]
#define SM_Z   16384    // 16384 : tanh tile [64][256]
#define SM_W   32768    // 16384 : W staging, 2 buffers x 8192 floats (4096 float2)
#define SM_A   49152    // 768   : normalized anchors [3][256]
#define SM_B1  49920    // 256
#define SM_B2  50176    // 256
#define SM_SS  50432    // 64    : per-row ||h||^2
#define SM_D0  50496    // 64    : per-row <h,a0>
#define SM_D1  50560
#define SM_D2  50624
#define SM_TOTALF 50688
#define SMEM_BYTES (SM_TOTALF * 4)

// W1/W2 pre-transposed to k-pair-major: g_Wt[kk*256 + n] = {W[n][2kk], W[n][2kk+1]}
__device__ __align__(16) float2 g_Wt1[128 * 256];
__device__ __align__(16) float2 g_Wt2[128 * 256];
__device__ __align__(16) float  g_an[3 * 256];

// ---------------------------------------------------------------- helpers
__device__ __forceinline__ void fma2(ull& d, ull a, ull b) {
    asm("fma.rn.f32x2 %0, %1, %2, %0;" : "+l"(d) : "l"(a), "l"(b));
}
__device__ __forceinline__ float pair_sum(ull v) {
    return __uint_as_float((unsigned)v) + __uint_as_float((unsigned)(v >> 32));
}
__device__ __forceinline__ void cp_async16(float* s, const float4* g) {
    unsigned sa = (unsigned)__cvta_generic_to_shared(s);
    asm volatile("cp.async.cg.shared.global [%0], [%1], 16;" :: "r"(sa), "l"(g));
}
__device__ __forceinline__ void cp_commit() { asm volatile("cp.async.commit_group;"); }
template <int N> __device__ __forceinline__ void cp_wait() {
    asm volatile("cp.async.wait_group %0;" :: "n"(N));
}
__device__ __forceinline__ void reduce4(float& a, float& b, float& c, float& d) {
#pragma unroll
    for (int off = 16; off > 0; off >>= 1) {
        a += __shfl_xor_sync(0xffffffffu, a, off);
        b += __shfl_xor_sync(0xffffffffu, b, off);
        c += __shfl_xor_sync(0xffffffffu, c, off);
        d += __shfl_xor_sync(0xffffffffu, d, off);
    }
}

// copy one 32KB chunk (16 kk-pairs x 256 cols of float2) into smem
__device__ __forceinline__ void copy_chunk(float* dst, const float4* src, int tid) {
#pragma unroll
    for (int q = 0; q < 8; q++)
        cp_async16(dst + (tid + 256 * q) * 4, src + tid + 256 * q);
}

// D[m, n] += sum_k A[m, k] * W[n, k]   with k-paired f32x2 accumulators.
// A_s: [64][256] fp32 row-major smem.  Bg4: k-pair-major float2 matrix (as float4*).
__device__ __forceinline__ void gemm64(const float* __restrict__ A_s,
                                       const float4* __restrict__ Bg4,
                                       float* wreg, ull (&acc)[8][8],
                                       int tid, int wy, int tx) {
#pragma unroll
    for (int r = 0; r < 8; r++)
#pragma unroll
        for (int j = 0; j < 8; j++) acc[r][j] = 0ull;

    copy_chunk(wreg, Bg4, tid);
    cp_commit();

#pragma unroll 1
    for (int c = 0; c < 8; c++) {
        if (c < 7) {
            copy_chunk(wreg + ((c + 1) & 1) * 8192, Bg4 + (c + 1) * 2048, tid);
            cp_commit();
            cp_wait<1>();
        } else {
            cp_wait<0>();
        }
        __syncthreads();

        const float* wb = wreg + (c & 1) * 8192;       // float2 region, as floats
        const float* Ab = A_s + wy * 8 * 256 + c * 32; // this warp's 8 rows, chunk k-base
#pragma unroll
        for (int kk = 0; kk < 16; kk++) {
            ull bv[8];
#pragma unroll
            for (int j = 0; j < 8; j++)
                bv[j] = *(const ull*)(wb + 2 * (kk * 256 + tx + 32 * j));
#pragma unroll
            for (int r = 0; r < 8; r++) {
                ull av = *(const ull*)(Ab + r * 256 + 2 * kk);
#pragma unroll
                for (int j = 0; j < 8; j++) fma2(acc[r][j], av, bv[j]);
            }
        }
        __syncthreads();
    }
}

// ---------------------------------------------------------------- prep kernel
__global__ void prep_kernel(const float* __restrict__ W1, const float* __restrict__ W2,
                            const float* __restrict__ anchors) {
    int t = blockIdx.x * blockDim.x + threadIdx.x;
    for (int i = t; i < 128 * 256; i += gridDim.x * blockDim.x) {
        int kk = i >> 8, n = i & 255;
        g_Wt1[i] = make_float2(W1[n * 256 + 2 * kk], W1[n * 256 + 2 * kk + 1]);
        g_Wt2[i] = make_float2(W2[n * 256 + 2 * kk], W2[n * 256 + 2 * kk + 1]);
    }
    if (blockIdx.x == 0 && threadIdx.x < 3) {
        int a = threadIdx.x;
        float ss = 0.f;
        for (int k = 0; k < 256; k++) { float v = anchors[a * 256 + k]; ss += v * v; }
        float inv = 1.f / fmaxf(sqrtf(ss), 1e-12f);
        for (int k = 0; k < 256; k++) g_an[a * 256 + k] = anchors[a * 256 + k] * inv;
    }
}

// ---------------------------------------------------------------- main fused kernel
__global__ void __launch_bounds__(NTHREADS, 1)
collapse_kernel(const float* __restrict__ h0, const float* __restrict__ b1,
                const float* __restrict__ b2, float* __restrict__ out) {
    extern __shared__ float sm[];
    float* h_s  = sm + SM_H;
    float* z_s  = sm + SM_Z;
    float* w_s  = sm + SM_W;
    float* a_s  = sm + SM_A;
    float* b1_s = sm + SM_B1;
    float* b2_s = sm + SM_B2;
    float* stss = sm + SM_SS;
    float* std0 = sm + SM_D0;
    float* std1 = sm + SM_D1;
    float* std2 = sm + SM_D2;

    const int tid  = threadIdx.x;
    const int wy   = tid >> 5;   // warp id = row group (8 rows)
    const int tx   = tid & 31;
    const int row0 = blockIdx.x * MTILE;

    // ---- load h tile, anchors, biases
    {
        const float4* hv = (const float4*)(h0 + (size_t)row0 * DIMN);
        float4* hs = (float4*)h_s;
#pragma unroll
        for (int q = 0; q < 16; q++) hs[tid + 256 * q] = hv[tid + 256 * q];
        if (tid < 192) ((float4*)a_s)[tid] = ((const float4*)g_an)[tid];
        if (tid < 64) ((float4*)b1_s)[tid] = ((const float4*)b1)[tid];
        else if (tid < 128) ((float4*)b2_s)[tid - 64] = ((const float4*)b2)[tid - 64];
    }
    __syncthreads();

    // ---- initial per-row stats: ||h||^2, <h, a_i>
#pragma unroll
    for (int r = 0; r < 8; r++) {
        int m = wy * 8 + r;
        float p0 = 0.f, p1 = 0.f, p2 = 0.f, p3 = 0.f;
#pragma unroll
        for (int j = 0; j < 8; j++) {
            int col = tx + 32 * j;
            float hv = h_s[m * 256 + col];
            p0 += hv * hv;
            p1 += hv * a_s[col];
            p2 += hv * a_s[256 + col];
            p3 += hv * a_s[512 + col];
        }
        reduce4(p0, p1, p2, p3);
        if (tx == 0) { stss[m] = p0; std0[m] = p1; std1[m] = p2; std2[m] = p3; }
    }

    ull acc[8][8];

    for (int l = 0; l < NLAYERS; l++) {
        __syncthreads();  // stats + h_s visible to all

        // ---- traces for this layer (one thread per row)
        if (tid < MTILE) {
            float ss = stss[tid];
            float inv = 1.f / fmaxf(sqrtf(ss), 1e-12f);
            float dts[3] = { std0[tid], std1[tid], std2[tid] };
            size_t base = (size_t)(l * B_TOTAL + row0 + tid) * 3;
#pragma unroll
            for (int a = 0; a < 3; a++) {
                float al = dts[a] * inv;
                float dv = 1.f - al;
                out[OUT_ALIGN + base + a] = al;
                out[OUT_DIV   + base + a] = dv;
                out[OUT_TEN   + base + a] = fabsf(dv);
            }
        }

        // ---- GEMM1: pre = h @ W1^T ; z = tanh(pre + b1)
        gemm64(h_s, (const float4*)g_Wt1, w_s, acc, tid, wy, tx);
#pragma unroll
        for (int r = 0; r < 8; r++) {
            int m = wy * 8 + r;
#pragma unroll
            for (int j = 0; j < 8; j++) {
                int col = tx + 32 * j;
                z_s[m * 256 + col] = tanhf(pair_sum(acc[r][j]) + b1_s[col]);
            }
        }
        __syncthreads();

        // ---- GEMM2: delta = z @ W2^T (+ b2 in epilogue)
        gemm64(z_s, (const float4*)g_Wt2, w_s, acc, tid, wy, tx);

        // ---- epilogue: force + update + clip + stats for next layer
#pragma unroll
        for (int r = 0; r < 8; r++) {
            int m = wy * 8 + r;
            float ss = stss[m], d0 = std0[m], d1 = std1[m], d2 = std2[m];
            float inv = 1.f / fmaxf(sqrtf(ss), 1e-12f);
            float dv0 = 1.f - d0 * inv, dv1 = 1.f - d1 * inv, dv2 = 1.f - d2 * inv;
            float nd0 = sqrtf(fmaxf(ss - 2.f * d0 + 1.f, 0.f));
            float nd1 = sqrtf(fmaxf(ss - 2.f * d1 + 1.f, 0.f));
            float nd2 = sqrtf(fmaxf(ss - 2.f * d2 + 1.f, 0.f));
            float ca0 = 0.1f * dv0 / fmaxf(nd0, 1e-12f);
            float ca1 = 0.1f * dv1 / fmaxf(nd1, 1e-12f);
            float ca2 = 0.1f * dv2 / fmaxf(nd2, 1e-12f);
            float hmul = 1.f - (ca0 + ca1 + ca2);

            float v[8];
            float p0 = 0.f, p1 = 0.f, p2 = 0.f, p3 = 0.f;
#pragma unroll
            for (int j = 0; j < 8; j++) {
                int col = tx + 32 * j;
                float hv = h_s[m * 256 + col];
                float dl = pair_sum(acc[r][j]) + b2_s[col];
                float a0 = a_s[col], a1 = a_s[256 + col], a2 = a_s[512 + col];
                float x = hv * hmul + dl + ca0 * a0 + ca1 * a1 + ca2 * a2;
                v[j] = x;
                p0 += x * x; p1 += x * a0; p2 += x * a1; p3 += x * a2;
            }
            reduce4(p0, p1, p2, p3);
            float n = sqrtf(p0);
            float s = (n > 10.f) ? (10.f / (n + 1e-8f)) : 1.f;
#pragma unroll
            for (int j = 0; j < 8; j++) h_s[m * 256 + tx + 32 * j] = v[j] * s;
            if (tx == 0) {
                stss[m] = p0 * s * s;
                std0[m] = p1 * s; std1[m] = p2 * s; std2[m] = p3 * s;
            }
        }
    }
    __syncthreads();

    // ---- store h_final
    {
        float4* ov = (float4*)(out + (size_t)row0 * DIMN);
        const float4* hs = (const float4*)h_s;
#pragma unroll
        for (int q = 0; q < 16; q++) ov[tid + 256 * q] = hs[tid + 256 * q];
    }
}

// ---------------------------------------------------------------- launch
extern "C" void kernel_launch(void* const* d_in, const int* in_sizes, int n_in,
                              void* d_out, int out_size) {
    const float* h0      = (const float*)d_in[0];
    const float* W1      = (const float*)d_in[1];
    const float* b1      = (const float*)d_in[2];
    const float* W2      = (const float*)d_in[3];
    const float* b2      = (const float*)d_in[4];
    const float* anchors = (const float*)d_in[5];
    float* out = (float*)d_out;

    (void)in_sizes; (void)n_in; (void)out_size;

    cudaFuncSetAttribute(collapse_kernel,
                         cudaFuncAttributeMaxDynamicSharedMemorySize, SMEM_BYTES);

    prep_kernel<<<64, 256>>>(W1, W2, anchors);
    collapse_kernel<<<B_TOTAL / MTILE, NTHREADS, SMEM_BYTES>>>(h0, b1, b2, out);
}

// round 9
// speedup vs baseline: 1.0564x; 1.0007x over previous
#include <cuda_runtime.h>
#include <cstdint>

typedef unsigned long long ull;

#define B_TOTAL   131072
#define DIMN      256
#define NLAYERS   6
#define MTILE     64
#define NTHREADS  256

// output layout: h_final [B,256] then aligns[6,B,3], divs[6,B,3], tens[6,B,3]
#define OUT_ALIGN 33554432
#define OUT_DIV   35913728
#define OUT_TEN   38273024

// smem float offsets
#define SM_H   0        // 16384 : h tile [64][256]
#define SM_Z   16384    // 16384 : tanh tile [64][256]
#define SM_W   32768    // 16384 : W staging, 2 buffers x 8192 floats (4096 float2)
#define SM_A   49152    // 768   : normalized anchors [3][256]
#define SM_B1  49920    // 256
#define SM_B2  50176    // 256
#define SM_SS  50432    // 64    : per-row ||h||^2
#define SM_D0  50496    // 64    : per-row <h,a0>
#define SM_D1  50560
#define SM_D2  50624
#define SM_TOTALF 50688
#define SMEM_BYTES (SM_TOTALF * 4)

// W1/W2 pre-transposed to k-pair-major: g_Wt[kk*256 + n] = {W[n][2kk], W[n][2kk+1]}
__device__ __align__(16) float2 g_Wt1[128 * 256];
__device__ __align__(16) float2 g_Wt2[128 * 256];
__device__ __align__(16) float  g_an[3 * 256];

// ---------------------------------------------------------------- helpers
__device__ __forceinline__ void fma2(ull& d, ull a, ull b) {
    asm("fma.rn.f32x2 %0, %1, %2, %0;" : "+l"(d) : "l"(a), "l"(b));
}
__device__ __forceinline__ float pair_sum(ull v) {
    return __uint_as_float((unsigned)v) + __uint_as_float((unsigned)(v >> 32));
}
__device__ __forceinline__ void cp_async16(float* s, const float4* g) {
    unsigned sa = (unsigned)__cvta_generic_to_shared(s);
    asm volatile("cp.async.cg.shared.global [%0], [%1], 16;" :: "r"(sa), "l"(g));
}
__device__ __forceinline__ void cp_commit() { asm volatile("cp.async.commit_group;"); }
template <int N> __device__ __forceinline__ void cp_wait() {
    asm volatile("cp.async.wait_group %0;" :: "n"(N));
}
__device__ __forceinline__ void reduce4(float& a, float& b, float& c, float& d) {
#pragma unroll
    for (int off = 16; off > 0; off >>= 1) {
        a += __shfl_xor_sync(0xffffffffu, a, off);
        b += __shfl_xor_sync(0xffffffffu, b, off);
        c += __shfl_xor_sync(0xffffffffu, c, off);
        d += __shfl_xor_sync(0xffffffffu, d, off);
    }
}

// copy one 32KB chunk (16 kk-pairs x 256 cols of float2) into smem
__device__ __forceinline__ void copy_chunk(float* dst, const float4* src, int tid) {
#pragma unroll
    for (int q = 0; q < 8; q++)
        cp_async16(dst + (tid + 256 * q) * 4, src + tid + 256 * q);
}

// D[m, n] += sum_k A[m, k] * W[n, k]   with k-paired f32x2 accumulators.
// A_s: [64][256] fp32 row-major smem.  Bg4: k-pair-major float2 matrix (as float4*).
__device__ __forceinline__ void gemm64(const float* __restrict__ A_s,
                                       const float4* __restrict__ Bg4,
                                       float* wreg, ull (&acc)[8][8],
                                       int tid, int wy, int tx) {
#pragma unroll
    for (int r = 0; r < 8; r++)
#pragma unroll
        for (int j = 0; j < 8; j++) acc[r][j] = 0ull;

    copy_chunk(wreg, Bg4, tid);
    cp_commit();

#pragma unroll 1
    for (int c = 0; c < 8; c++) {
        if (c < 7) {
            copy_chunk(wreg + ((c + 1) & 1) * 8192, Bg4 + (c + 1) * 2048, tid);
            cp_commit();
            cp_wait<1>();
        } else {
            cp_wait<0>();
        }
        __syncthreads();

        const float* wb = wreg + (c & 1) * 8192;       // float2 region, as floats
        const float* Ab = A_s + wy * 8 * 256 + c * 32; // this warp's 8 rows, chunk k-base
#pragma unroll
        for (int kk = 0; kk < 16; kk++) {
            ull bv[8];
#pragma unroll
            for (int j = 0; j < 8; j++)
                bv[j] = *(const ull*)(wb + 2 * (kk * 256 + tx + 32 * j));
#pragma unroll
            for (int r = 0; r < 8; r++) {
                ull av = *(const ull*)(Ab + r * 256 + 2 * kk);
#pragma unroll
                for (int j = 0; j < 8; j++) fma2(acc[r][j], av, bv[j]);
            }
        }
        __syncthreads();
    }
}

// ---------------------------------------------------------------- prep kernel
__global__ void prep_kernel(const float* __restrict__ W1, const float* __restrict__ W2,
                            const float* __restrict__ anchors) {
    int t = blockIdx.x * blockDim.x + threadIdx.x;
    for (int i = t; i < 128 * 256; i += gridDim.x * blockDim.x) {
        int kk = i >> 8, n = i & 255;
        g_Wt1[i] = make_float2(W1[n * 256 + 2 * kk], W1[n * 256 + 2 * kk + 1]);
        g_Wt2[i] = make_float2(W2[n * 256 + 2 * kk], W2[n * 256 + 2 * kk + 1]);
    }
    if (blockIdx.x == 0 && threadIdx.x < 3) {
        int a = threadIdx.x;
        float ss = 0.f;
        for (int k = 0; k < 256; k++) { float v = anchors[a * 256 + k]; ss += v * v; }
        float inv = 1.f / fmaxf(sqrtf(ss), 1e-12f);
        for (int k = 0; k < 256; k++) g_an[a * 256 + k] = anchors[a * 256 + k] * inv;
    }
}

// ---------------------------------------------------------------- main fused kernel
__global__ void __launch_bounds__(NTHREADS, 1)
collapse_kernel(const float* __restrict__ h0, const float* __restrict__ b1,
                const float* __restrict__ b2, float* __restrict__ out) {
    extern __shared__ float sm[];
    float* h_s  = sm + SM_H;
    float* z_s  = sm + SM_Z;
    float* w_s  = sm + SM_W;
    float* a_s  = sm + SM_A;
    float* b1_s = sm + SM_B1;
    float* b2_s = sm + SM_B2;
    float* stss = sm + SM_SS;
    float* std0 = sm + SM_D0;
    float* std1 = sm + SM_D1;
    float* std2 = sm + SM_D2;

    const int tid  = threadIdx.x;
    const int wy   = tid >> 5;   // warp id = row group (8 rows)
    const int tx   = tid & 31;
    const int row0 = blockIdx.x * MTILE;

    // ---- load h tile, anchors, biases
    {
        const float4* hv = (const float4*)(h0 + (size_t)row0 * DIMN);
        float4* hs = (float4*)h_s;
#pragma unroll
        for (int q = 0; q < 16; q++) hs[tid + 256 * q] = hv[tid + 256 * q];
        if (tid < 192) ((float4*)a_s)[tid] = ((const float4*)g_an)[tid];
        if (tid < 64) ((float4*)b1_s)[tid] = ((const float4*)b1)[tid];
        else if (tid < 128) ((float4*)b2_s)[tid - 64] = ((const float4*)b2)[tid - 64];
    }
    __syncthreads();

    // ---- initial per-row stats: ||h||^2, <h, a_i>
#pragma unroll
    for (int r = 0; r < 8; r++) {
        int m = wy * 8 + r;
        float p0 = 0.f, p1 = 0.f, p2 = 0.f, p3 = 0.f;
#pragma unroll
        for (int j = 0; j < 8; j++) {
            int col = tx + 32 * j;
            float hv = h_s[m * 256 + col];
            p0 += hv * hv;
            p1 += hv * a_s[col];
            p2 += hv * a_s[256 + col];
            p3 += hv * a_s[512 + col];
        }
        reduce4(p0, p1, p2, p3);
        if (tx == 0) { stss[m] = p0; std0[m] = p1; std1[m] = p2; std2[m] = p3; }
    }

    ull acc[8][8];

    for (int l = 0; l < NLAYERS; l++) {
        __syncthreads();  // stats + h_s visible to all

        // ---- traces for this layer (one thread per row)
        if (tid < MTILE) {
            float ss = stss[tid];
            float inv = 1.f / fmaxf(sqrtf(ss), 1e-12f);
            float dts[3] = { std0[tid], std1[tid], std2[tid] };
            size_t base = (size_t)(l * B_TOTAL + row0 + tid) * 3;
#pragma unroll
            for (int a = 0; a < 3; a++) {
                float al = dts[a] * inv;
                float dv = 1.f - al;
                out[OUT_ALIGN + base + a] = al;
                out[OUT_DIV   + base + a] = dv;
                out[OUT_TEN   + base + a] = fabsf(dv);
            }
        }

        // ---- GEMM1: pre = h @ W1^T ; z = tanh(pre + b1)
        gemm64(h_s, (const float4*)g_Wt1, w_s, acc, tid, wy, tx);
#pragma unroll
        for (int r = 0; r < 8; r++) {
            int m = wy * 8 + r;
#pragma unroll
            for (int j = 0; j < 8; j++) {
                int col = tx + 32 * j;
                z_s[m * 256 + col] = tanhf(pair_sum(acc[r][j]) + b1_s[col]);
            }
        }
        __syncthreads();

        // ---- GEMM2: delta = z @ W2^T (+ b2 in epilogue)
        gemm64(z_s, (const float4*)g_Wt2, w_s, acc, tid, wy, tx);

        // ---- epilogue: force + update + clip + stats for next layer
#pragma unroll
        for (int r = 0; r < 8; r++) {
            int m = wy * 8 + r;
            float ss = stss[m], d0 = std0[m], d1 = std1[m], d2 = std2[m];
            float inv = 1.f / fmaxf(sqrtf(ss), 1e-12f);
            float dv0 = 1.f - d0 * inv, dv1 = 1.f - d1 * inv, dv2 = 1.f - d2 * inv;
            float nd0 = sqrtf(fmaxf(ss - 2.f * d0 + 1.f, 0.f));
            float nd1 = sqrtf(fmaxf(ss - 2.f * d1 + 1.f, 0.f));
            float nd2 = sqrtf(fmaxf(ss - 2.f * d2 + 1.f, 0.f));
            float ca0 = 0.1f * dv0 / fmaxf(nd0, 1e-12f);
            float ca1 = 0.1f * dv1 / fmaxf(nd1, 1e-12f);
            float ca2 = 0.1f * dv2 / fmaxf(nd2, 1e-12f);
            float hmul = 1.f - (ca0 + ca1 + ca2);

            float v[8];
            float p0 = 0.f, p1 = 0.f, p2 = 0.f, p3 = 0.f;
#pragma unroll
            for (int j = 0; j < 8; j++) {
                int col = tx + 32 * j;
                float hv = h_s[m * 256 + col];
                float dl = pair_sum(acc[r][j]) + b2_s[col];
                float a0 = a_s[col], a1 = a_s[256 + col], a2 = a_s[512 + col];
                float x = hv * hmul + dl + ca0 * a0 + ca1 * a1 + ca2 * a2;
                v[j] = x;
                p0 += x * x; p1 += x * a0; p2 += x * a1; p3 += x * a2;
            }
            reduce4(p0, p1, p2, p3);
            float n = sqrtf(p0);
            float s = (n > 10.f) ? (10.f / (n + 1e-8f)) : 1.f;
#pragma unroll
            for (int j = 0; j < 8; j++) h_s[m * 256 + tx + 32 * j] = v[j] * s;
            if (tx == 0) {
                stss[m] = p0 * s * s;
                std0[m] = p1 * s; std1[m] = p2 * s; std2[m] = p3 * s;
            }
        }
    }
    __syncthreads();

    // ---- store h_final
    {
        float4* ov = (float4*)(out + (size_t)row0 * DIMN);
        const float4* hs = (const float4*)h_s;
#pragma unroll
        for (int q = 0; q < 16; q++) ov[tid + 256 * q] = hs[tid + 256 * q];
    }
}

// ---------------------------------------------------------------- launch
extern "C" void kernel_launch(void* const* d_in, const int* in_sizes, int n_in,
                              void* d_out, int out_size) {
    const float* h0      = (const float*)d_in[0];
    const float* W1      = (const float*)d_in[1];
    const float* b1      = (const float*)d_in[2];
    const float* W2      = (const float*)d_in[3];
    const float* b2      = (const float*)d_in[4];
    const float* anchors = (const float*)d_in[5];
    float* out = (float*)d_out;

    (void)in_sizes; (void)n_in; (void)out_size;

    cudaFuncSetAttribute(collapse_kernel,
                         cudaFuncAttributeMaxDynamicSharedMemorySize, SMEM_BYTES);

    prep_kernel<<<64, 256>>>(W1, W2, anchors);
    collapse_kernel<<<B_TOTAL / MTILE, NTHREADS, SMEM_BYTES>>>(h0, b1, b2, out);
}

// round 14
// speedup vs baseline: 1.6668x; 1.5777x over previous
#include <cuda_runtime.h>
#include <cuda_bf16.h>
#include <cstdint>

#define NLAYERS 6
#define B_TOTAL 131072

// output layout: h_final [B,256] then aligns[6,B,3], divs[6,B,3], tens[6,B,3]
#define OUT_ALIGN 33554432
#define OUT_DIV   35913728
#define OUT_TEN   38273024

// SMEM byte offsets
#define SB_BUF  0        // 2 x 36864 : W chunk [256 n][pitch 72 bf16 = 144 B]
#define SB_HHI  73728    // 64 rows x 528 B : h/z hi plane (pitch 264 bf16)
#define SB_HLO  107520   // lo plane
#define SB_C1   141312   // 256 x float4 (a0, a1, a2, b1)
#define SB_B2   145408   // 256 floats
#define SB_STAT 146432   // 2 bufs x 256 floats (ss,d0,d1,d2 x 64 rows)
#define SB_SROW 148480   // 64 floats deferred clip scale
#define SMEM_DYN 148736

// W pre-split: [mat 2][split 2 (hi,lo)][n 256][k 256] bf16
__device__ __align__(16) __nv_bfloat16 g_Wb[262144];
__device__ __align__(16) float4 g_c1[256];   // normalized anchors (a0,a1,a2,0)

// ---------------------------------------------------------------- helpers
__device__ __forceinline__ uint32_t smem_u32(const void* p) {
    uint32_t a;
    asm("{ .reg .u64 t; cvta.to.shared.u64 t, %1; cvt.u32.u64 %0, t; }" : "=r"(a) : "l"(p));
    return a;
}
__device__ __forceinline__ float fast_tanh(float x) {
    float a = fabsf(x);
    float t = __expf(-2.0f * a);
    float r = __fdividef(1.0f - t, 1.0f + t);
    return copysignf(r, x);
}
__device__ __forceinline__ void split2(float x0, float x1, uint32_t& hi, uint32_t& lo) {
    __nv_bfloat16 h0 = __float2bfloat16(x0), h1 = __float2bfloat16(x1);
    float l0 = x0 - __bfloat162float(h0), l1 = x1 - __bfloat162float(h1);
    __nv_bfloat16 L0 = __float2bfloat16(l0), L1 = __float2bfloat16(l1);
    hi = (uint32_t)__bfloat16_as_ushort(h0) | ((uint32_t)__bfloat16_as_ushort(h1) << 16);
    lo = (uint32_t)__bfloat16_as_ushort(L0) | ((uint32_t)__bfloat16_as_ushort(L1) << 16);
}
__device__ __forceinline__ void unpack2(uint32_t u, float& a, float& b) {
    a = __bfloat162float(__ushort_as_bfloat16((unsigned short)(u & 0xFFFFu)));
    b = __bfloat162float(__ushort_as_bfloat16((unsigned short)(u >> 16)));
}
__device__ __forceinline__ void cp16(uint32_t dst, const void* src) {
    asm volatile("cp.async.cg.shared.global [%0], [%1], 16;" :: "r"(dst), "l"(src));
}
#define CP_COMMIT() asm volatile("cp.async.commit_group;" ::: "memory")
#define CP_WAIT0()  asm volatile("cp.async.wait_group 0;" ::: "memory")

#define LDSM4(r, addr) asm volatile( \
    "ldmatrix.sync.aligned.m8n8.x4.shared.b16 {%0,%1,%2,%3}, [%4];" \
    : "=r"((r)[0]), "=r"((r)[1]), "=r"((r)[2]), "=r"((r)[3]) : "r"(addr))

#define MMA(d, a, b0, b1) asm volatile( \
    "mma.sync.aligned.m16n8k16.row.col.f32.bf16.bf16.f32 " \
    "{%0,%1,%2,%3}, {%4,%5,%6,%7}, {%8,%9}, {%0,%1,%2,%3};" \
    : "+f"((d)[0]), "+f"((d)[1]), "+f"((d)[2]), "+f"((d)[3]) \
    : "r"((a)[0]), "r"((a)[1]), "r"((a)[2]), "r"((a)[3]), "r"(b0), "r"(b1))

// one 32KB chunk [256 n][64 k] bf16 -> smem pitch 144 B
__device__ __forceinline__ void copy_chunk(uint32_t dst, const __nv_bfloat16* src, int tid) {
#pragma unroll
    for (int q = 0; q < 8; q++) {
        int u = tid + 256 * q;
        int n = u >> 3, j = u & 7;
        cp16(dst + (uint32_t)(n * 144 + j * 16), src + n * 256 + j * 8);
    }
}

// acc[16][4] += (Ahi+Alo) @ (Whi+Wlo)^T via 3 split products. Chunk c: split=c&1, kc=c>>1.
__device__ __forceinline__ void do_gemm(float (&acc)[16][4], uint32_t sb,
                                        const __nv_bfloat16* gW,
                                        const __nv_bfloat16* next0, int tid) {
    const int lane = tid & 31, w = tid >> 5, mw = w & 1, nw = w >> 1;
    const uint32_t aRow = (uint32_t)((mw * 32 + (lane & 15)) * 528 + (lane >> 4) * 16);
    const uint32_t bRow = (uint32_t)((nw * 64 + (lane & 7)) * 144 + (lane >> 3) * 16);
#pragma unroll 1
    for (int c = 0; c < 8; c++) {
        CP_WAIT0();
        __syncthreads();
        if (c < 7)
            copy_chunk(sb + SB_BUF + (uint32_t)((c + 1) & 1) * 36864u,
                       gW + ((c + 1) & 1) * 65536 + ((c + 1) >> 1) * 64, tid);
        else if (next0)
            copy_chunk(sb + SB_BUF, next0, tid);
        CP_COMMIT();

        const int kc = c >> 1, hiW = !(c & 1);
        const uint32_t bB = sb + SB_BUF + (uint32_t)(c & 1) * 36864u + bRow;
#pragma unroll
        for (int k32 = 0; k32 < 2; k32++) {
            uint32_t bfr[8][4];
#pragma unroll
            for (int nt = 0; nt < 8; nt++)
                LDSM4(bfr[nt], bB + (uint32_t)(nt * 1152 + k32 * 64));
#pragma unroll
            for (int p = 0; p < 2; p++) {
                if (p == 0 || hiW) {
                    uint32_t pl = sb + (uint32_t)((hiW && p == 1) ? SB_HLO : SB_HHI)
                                + aRow + (uint32_t)(kc * 128 + k32 * 64);
                    uint32_t afr[2][2][4];
#pragma unroll
                    for (int mg = 0; mg < 2; mg++)
#pragma unroll
                        for (int kt = 0; kt < 2; kt++)
                            LDSM4(afr[mg][kt], pl + (uint32_t)(mg * 8448 + kt * 32));
#pragma unroll
                    for (int mg = 0; mg < 2; mg++)
#pragma unroll
                        for (int nt = 0; nt < 8; nt++)
#pragma unroll
                            for (int kt = 0; kt < 2; kt++)
                                MMA(acc[mg * 8 + nt], afr[mg][kt],
                                    bfr[nt][2 * kt], bfr[nt][2 * kt + 1]);
                }
            }
        }
    }
    __syncthreads();
}

// ---------------------------------------------------------------- prep kernel
__global__ void prep_kernel(const float* __restrict__ W1, const float* __restrict__ W2,
                            const float* __restrict__ anchors) {
    int stride = gridDim.x * blockDim.x;
    for (int i = blockIdx.x * blockDim.x + threadIdx.x; i < 131072; i += stride) {
        int mat = i >> 16, n = (i >> 8) & 255, k = i & 255;
        float x = (mat ? W2 : W1)[n * 256 + k];
        __nv_bfloat16 hi = __float2bfloat16(x);
        g_Wb[mat * 131072 + n * 256 + k] = hi;
        g_Wb[mat * 131072 + 65536 + n * 256 + k] =
            __float2bfloat16(x - __bfloat162float(hi));
    }
    if (blockIdx.x == 0 && threadIdx.x < 256) {
        float inv[3];
#pragma unroll
        for (int a = 0; a < 3; a++) {
            float ss = 0.f;
            for (int k = 0; k < 256; k++) { float v = anchors[a * 256 + k]; ss += v * v; }
            inv[a] = 1.f / fmaxf(sqrtf(ss), 1e-12f);
        }
        int col = threadIdx.x;
        g_c1[col] = make_float4(anchors[col] * inv[0], anchors[256 + col] * inv[1],
                                anchors[512 + col] * inv[2], 0.f);
    }
}

// ---------------------------------------------------------------- main kernel
__global__ void __launch_bounds__(256, 1)
collapse_mma(const float* __restrict__ h0g, const float* __restrict__ b1g,
             const float* __restrict__ b2g, float* __restrict__ out) {
    extern __shared__ char smb[];
    const uint32_t sb = smem_u32(smb);
    float4*   c1s  = (float4*)(smb + SB_C1);
    float*    b2s  = (float*)(smb + SB_B2);
    float*    stat = (float*)(smb + SB_STAT);
    float*    srow = (float*)(smb + SB_SROW);
    uint32_t* hh   = (uint32_t*)(smb + SB_HHI);   // pitch 132 u32 per row
    uint32_t* hl   = (uint32_t*)(smb + SB_HLO);

    const int tid = threadIdx.x, lane = tid & 31, w = tid >> 5;
    const int mw = w & 1, nw = w >> 1;
    const int row0 = blockIdx.x * 64;

    copy_chunk(sb + SB_BUF, g_Wb, tid);     // GEMM1 chunk 0
    CP_COMMIT();

    {
        float4 an = g_c1[tid];
        c1s[tid] = make_float4(an.x, an.y, an.z, b1g[tid]);
        b2s[tid] = b2g[tid];
        stat[tid] = 0.f; stat[256 + tid] = 0.f;
        if (tid < 64) srow[tid] = 1.f;
    }
    __syncthreads();

    // ---- init: h0 -> stats + split planes (4 threads per row)
    {
        int row = tid >> 2, q = tid & 3;
        const float2* src = (const float2*)(h0g + (size_t)(row0 + row) * 256 + q * 64);
        float p0 = 0, p1 = 0, p2 = 0, p3 = 0;
#pragma unroll
        for (int j = 0; j < 32; j++) {
            float2 v = src[j];
            int col = q * 64 + 2 * j;
            float4 ca = c1s[col], cb = c1s[col + 1];
            p0 += v.x * v.x + v.y * v.y;
            p1 += v.x * ca.x + v.y * cb.x;
            p2 += v.x * ca.y + v.y * cb.y;
            p3 += v.x * ca.z + v.y * cb.z;
            uint32_t ph, pv; split2(v.x, v.y, ph, pv);
            hh[row * 132 + q * 32 + j] = ph;
            hl[row * 132 + q * 32 + j] = pv;
        }
        p0 += __shfl_xor_sync(~0u, p0, 1); p0 += __shfl_xor_sync(~0u, p0, 2);
        p1 += __shfl_xor_sync(~0u, p1, 1); p1 += __shfl_xor_sync(~0u, p1, 2);
        p2 += __shfl_xor_sync(~0u, p2, 1); p2 += __shfl_xor_sync(~0u, p2, 2);
        p3 += __shfl_xor_sync(~0u, p3, 1); p3 += __shfl_xor_sync(~0u, p3, 2);
        if ((lane & 3) == 0) {
            atomicAdd(&stat[row], p0);       atomicAdd(&stat[64 + row], p1);
            atomicAdd(&stat[128 + row], p2); atomicAdd(&stat[192 + row], p3);
        }
    }
    __syncthreads();

    float acc[16][4];

#pragma unroll 1
    for (int l = 0; l < NLAYERS; l++) {
        float* stC = stat + (l & 1) * 256;
        float* stN = stat + ((l + 1) & 1) * 256;

        // ---- traces (stats already clip-scaled)
        if (tid < 64) {
            float inv = 1.f / fmaxf(sqrtf(stC[tid]), 1e-12f);
            size_t base = (size_t)(l * B_TOTAL + row0 + tid) * 3;
#pragma unroll
            for (int a = 0; a < 3; a++) {
                float al = stC[(a + 1) * 64 + tid] * inv;
                float dv = 1.f - al;
                out[OUT_ALIGN + base + a] = al;
                out[OUT_DIV + base + a] = dv;
                out[OUT_TEN + base + a] = fabsf(dv);
            }
        }

        // ---- GEMM1: acc = x_unscaled @ W1^T  (prefetches W2 chunk0 at end)
#pragma unroll
        for (int t = 0; t < 16; t++)
#pragma unroll
            for (int e = 0; e < 4; e++) acc[t][e] = 0.f;
        do_gemm(acc, sb, g_Wb, g_Wb + 131072, tid);

        // ---- per-row force coefficients
        float hmul[4], k0c[4], k1c[4], k2c[4], sR[4];
#pragma unroll
        for (int ridx = 0; ridx < 4; ridx++) {
            int row = mw * 32 + (ridx >> 1) * 16 + (ridx & 1) * 8 + (lane >> 2);
            float ss = stC[row], d0 = stC[64 + row], d1 = stC[128 + row], d2 = stC[192 + row];
            float inv = 1.f / fmaxf(sqrtf(ss), 1e-12f);
            float c0 = 0.1f * (1.f - d0 * inv) / fmaxf(sqrtf(fmaxf(ss - 2.f * d0 + 1.f, 0.f)), 1e-12f);
            float c1 = 0.1f * (1.f - d1 * inv) / fmaxf(sqrtf(fmaxf(ss - 2.f * d1 + 1.f, 0.f)), 1e-12f);
            float c2 = 0.1f * (1.f - d2 * inv) / fmaxf(sqrtf(fmaxf(ss - 2.f * d2 + 1.f, 0.f)), 1e-12f);
            k0c[ridx] = c0; k1c[ridx] = c1; k2c[ridx] = c2;
            hmul[ridx] = 1.f - (c0 + c1 + c2);
            sR[ridx] = srow[row];
        }

        // ---- tanh phase: z -> planes; acc := force + b2 (GEMM2 accumulates onto it)
#pragma unroll
        for (int mg = 0; mg < 2; mg++)
#pragma unroll
            for (int nt = 0; nt < 8; nt++) {
                int tile = mg * 8 + nt;
#pragma unroll
                for (int rh = 0; rh < 2; rh++) {
                    int ridx = mg * 2 + rh;
                    int rowi = mw * 32 + mg * 16 + rh * 8 + (lane >> 2);
                    int colp = nw * 64 + nt * 8 + (lane & 3) * 2;
                    int hpos = rowi * 132 + (colp >> 1);
                    float4 ca = c1s[colp], cb = c1s[colp + 1];
                    float pre0 = acc[tile][rh * 2 + 0] * sR[ridx] + ca.w;
                    float pre1 = acc[tile][rh * 2 + 1] * sR[ridx] + cb.w;
                    float ha, hb, la, lb;
                    unpack2(hh[hpos], ha, hb); unpack2(hl[hpos], la, lb);
                    float h0v = sR[ridx] * (ha + la), h1v = sR[ridx] * (hb + lb);
                    acc[tile][rh * 2 + 0] = h0v * hmul[ridx] + k0c[ridx] * ca.x
                        + k1c[ridx] * ca.y + k2c[ridx] * ca.z + b2s[colp];
                    acc[tile][rh * 2 + 1] = h1v * hmul[ridx] + k0c[ridx] * cb.x
                        + k1c[ridx] * cb.y + k2c[ridx] * cb.z + b2s[colp + 1];
                    uint32_t ph, pv;
                    split2(fast_tanh(pre0), fast_tanh(pre1), ph, pv);
                    hh[hpos] = ph; hl[hpos] = pv;
                }
            }
        stN[tid] = 0.f;

        // ---- GEMM2: acc += z @ W2^T  (prefetches next layer's W1 chunk0)
        do_gemm(acc, sb, g_Wb + 131072,
                (l < NLAYERS - 1) ? g_Wb : (const __nv_bfloat16*)0, tid);

        // ---- epilogue: x = acc; stats; split-store into planes
        {
            float p[4][4];
#pragma unroll
            for (int i = 0; i < 4; i++)
#pragma unroll
                for (int s = 0; s < 4; s++) p[i][s] = 0.f;
#pragma unroll
            for (int mg = 0; mg < 2; mg++)
#pragma unroll
                for (int nt = 0; nt < 8; nt++) {
                    int tile = mg * 8 + nt;
#pragma unroll
                    for (int rh = 0; rh < 2; rh++) {
                        int ridx = mg * 2 + rh;
                        int rowi = mw * 32 + mg * 16 + rh * 8 + (lane >> 2);
                        int colp = nw * 64 + nt * 8 + (lane & 3) * 2;
                        float4 ca = c1s[colp], cb = c1s[colp + 1];
                        float x0 = acc[tile][rh * 2 + 0], x1 = acc[tile][rh * 2 + 1];
                        p[ridx][0] += x0 * x0 + x1 * x1;
                        p[ridx][1] += x0 * ca.x + x1 * cb.x;
                        p[ridx][2] += x0 * ca.y + x1 * cb.y;
                        p[ridx][3] += x0 * ca.z + x1 * cb.z;
                        uint32_t ph, pv; split2(x0, x1, ph, pv);
                        hh[rowi * 132 + (colp >> 1)] = ph;
                        hl[rowi * 132 + (colp >> 1)] = pv;
                    }
                }
#pragma unroll
            for (int i = 0; i < 4; i++)
#pragma unroll
                for (int s = 0; s < 4; s++) {
                    p[i][s] += __shfl_xor_sync(~0u, p[i][s], 1);
                    p[i][s] += __shfl_xor_sync(~0u, p[i][s], 2);
                }
            if ((lane & 3) == 0) {
#pragma unroll
                for (int ridx = 0; ridx < 4; ridx++) {
                    int rowi = mw * 32 + (ridx >> 1) * 16 + (ridx & 1) * 8 + (lane >> 2);
                    atomicAdd(&stN[rowi], p[ridx][0]);
                    atomicAdd(&stN[64 + rowi], p[ridx][1]);
                    atomicAdd(&stN[128 + rowi], p[ridx][2]);
                    atomicAdd(&stN[192 + rowi], p[ridx][3]);
                }
            }
        }
        __syncthreads();

        // ---- finalize: deferred clip scale; scale stats
        if (tid < 64) {
            float P = stN[tid];
            float n = sqrtf(P);
            float s = (n > 10.f) ? (10.f / (n + 1e-8f)) : 1.f;
            srow[tid] = s;
            stN[tid] = P * s * s;
            stN[64 + tid] *= s; stN[128 + tid] *= s; stN[192 + tid] *= s;
        }
        __syncthreads();
    }

    // ---- store h_final = s * (hi + lo)
    {
        int row = tid >> 2, q = tid & 3;
        float s = srow[row];
        float2* dst = (float2*)(out + (size_t)(row0 + row) * 256 + q * 64);
#pragma unroll
        for (int j = 0; j < 32; j++) {
            float ha, hb, la, lb;
            unpack2(hh[row * 132 + q * 32 + j], ha, hb);
            unpack2(hl[row * 132 + q * 32 + j], la, lb);
            dst[j] = make_float2(s * (ha + la), s * (hb + lb));
        }
    }
}

// ---------------------------------------------------------------- launch
extern "C" void kernel_launch(void* const* d_in, const int* in_sizes, int n_in,
                              void* d_out, int out_size) {
    const float* h0      = (const float*)d_in[0];
    const float* W1      = (const float*)d_in[1];
    const float* b1      = (const float*)d_in[2];
    const float* W2      = (const float*)d_in[3];
    const float* b2      = (const float*)d_in[4];
    const float* anchors = (const float*)d_in[5];
    float* out = (float*)d_out;
    (void)in_sizes; (void)n_in; (void)out_size;

    cudaFuncSetAttribute(collapse_mma,
                         cudaFuncAttributeMaxDynamicSharedMemorySize, SMEM_DYN);

    prep_kernel<<<64, 256>>>(W1, W2, anchors);
    collapse_mma<<<B_TOTAL / 64, 256, SMEM_DYN>>>(h0, b1, b2, out);
}